// round 6
// baseline (speedup 1.0000x reference)
#include <cuda_runtime.h>
#include <cuda_bf16.h>

// Problem constants (match reference)
#define SIZE     16384      // 128*128 points per batch
#define KNN      16
#define ND       5          // num derivatives (order 2, 2D)
#define NBATCH   32
#define CHUNKS   4          // CTAs per batch -> grid 128 (single wave)
#define CTA_PTS  (SIZE / CHUNKS)   // 4096 points per CTA
#define NTHREADS 512
#define PTS_PER_THREAD (CTA_PTS / NTHREADS)  // 8
#define NPAIRS   (PTS_PER_THREAD / 2)        // 4

// Dynamic smem: float2 pxy[SIZE] (128KB) + float sv[SIZE] (64KB)
#define SMEM_BYTES (SIZE * sizeof(float2) + SIZE * sizeof(float))  // 196608

typedef unsigned long long u64;

// ---------------------------------------------------------------------------
// f32x2 packed primitives (sm_100+; ptxas never emits these from C++)
// ---------------------------------------------------------------------------
__device__ __forceinline__ float frcp_fast(float x) {
    float r; asm("rcp.approx.f32 %0, %1;" : "=f"(r) : "f"(x)); return r;
}
__device__ __forceinline__ u64 pk(float lo, float hi) {
    u64 r;
    asm("mov.b64 %0, {%1, %2};" : "=l"(r)
        : "r"(__float_as_uint(lo)), "r"(__float_as_uint(hi)));
    return r;
}
__device__ __forceinline__ void upk(float& lo, float& hi, u64 v) {
    unsigned a, b_;
    asm("mov.b64 {%0, %1}, %2;" : "=r"(a), "=r"(b_) : "l"(v));
    lo = __uint_as_float(a); hi = __uint_as_float(b_);
}
__device__ __forceinline__ u64 mul2(u64 a, u64 b) {
    u64 d; asm("mul.rn.f32x2 %0, %1, %2;" : "=l"(d) : "l"(a), "l"(b)); return d;
}
__device__ __forceinline__ u64 add2(u64 a, u64 b) {
    u64 d; asm("add.rn.f32x2 %0, %1, %2;" : "=l"(d) : "l"(a), "l"(b)); return d;
}
__device__ __forceinline__ u64 fma2(u64 a, u64 b, u64 c) {
    u64 d; asm("fma.rn.f32x2 %0, %1, %2, %3;" : "=l"(d) : "l"(a), "l"(b), "l"(c)); return d;
}
__device__ __forceinline__ u64 rcp2(u64 v) {
    float lo, hi; upk(lo, hi, v);
    return pk(frcp_fast(lo), frcp_fast(hi));
}
#define SGN2 0x8000000080000000ull   // packed sign flip (alu pipe, not fma)

// ---------------------------------------------------------------------------
// Primary kernel: full batch in 192 KB smem; packed f32x2 math on point pairs
// ---------------------------------------------------------------------------
__global__ void __launch_bounds__(NTHREADS, 1)
tp_layer_smem_kernel(const float* __restrict__ x,
                     const float* __restrict__ points,
                     const int*   __restrict__ edge_index,
                     const float* __restrict__ dt_p,
                     const float* __restrict__ dist,
                     const float* __restrict__ weight,
                     float* __restrict__ out)
{
    extern __shared__ float smem[];
    float2* pxy = reinterpret_cast<float2*>(smem);          // [SIZE]
    float*  sv  = smem + 2 * SIZE;                           // [SIZE]

    const int b     = blockIdx.x / CHUNKS;
    const int chunk = blockIdx.x % CHUNKS;
    const int tid   = threadIdx.x;

    const float* pts_b = points + (size_t)b * SIZE * 2;
    const float* x_b   = x + (size_t)b * SIZE;

    // Stage batch into smem: coalesced float4 copies (layout identical).
    {
        float4* dstp = reinterpret_cast<float4*>(pxy);
        const float4* srcp = reinterpret_cast<const float4*>(pts_b);
        #pragma unroll
        for (int i = 0; i < (SIZE * 2 / 4) / NTHREADS; ++i)   // 16 iters
            dstp[tid + i * NTHREADS] = srcp[tid + i * NTHREADS];

        float4* dstx = reinterpret_cast<float4*>(sv);
        const float4* srcx = reinterpret_cast<const float4*>(x_b);
        #pragma unroll
        for (int i = 0; i < (SIZE / 4) / NTHREADS; ++i)       // 8 iters
            dstx[tid + i * NTHREADS] = srcx[tid + i * NTHREADS];
    }
    __syncthreads();

    const float dt = dt_p[0];
    // packed per-derivative weights (same value in both lanes)
    u64 wpk[ND];
    #pragma unroll
    for (int i = 0; i < ND; ++i) wpk[i] = pk(weight[i], weight[i]);
    const u64 HALF2  = pk(0.5f, 0.5f);
    const u64 RIDGE2 = pk(1e-6f, 1e-6f);

    const int s_base = chunk * CTA_PTS;
    const int*   eidx_g = edge_index + (size_t)b * SIZE * KNN;
    const float* dist_g = dist       + (size_t)b * SIZE * KNN;

    #pragma unroll 1
    for (int pr = 0; pr < NPAIRS; ++pr) {
        const int s1 = s_base + tid + (2 * pr)     * NTHREADS;
        const int s2 = s_base + tid + (2 * pr + 1) * NTHREADS;

        const float2 pc1 = pxy[s1];  const float vc1 = sv[s1];
        const float2 pc2 = pxy[s2];  const float vc2 = sv[s2];

        const int4*   ei4a = reinterpret_cast<const int4*>(eidx_g + (size_t)s1 * KNN);
        const int4*   ei4b = reinterpret_cast<const int4*>(eidx_g + (size_t)s2 * KNN);
        const float4* dw4a = reinterpret_cast<const float4*>(dist_g + (size_t)s1 * KNN);
        const float4* dw4b = reinterpret_cast<const float4*>(dist_g + (size_t)s2 * KNN);

        // Packed upper-triangle normal equations M[i][j] (j>=i) + rhs bv[i].
        u64 M[ND][ND];
        u64 bv[ND];
        #pragma unroll
        for (int i = 0; i < ND; ++i) {
            bv[i] = 0ull;
            #pragma unroll
            for (int j = i; j < ND; ++j) M[i][j] = 0ull;
        }

        #pragma unroll
        for (int g = 0; g < 4; ++g) {
            const int4   eia = ei4a[g];
            const int4   eib = ei4b[g];
            const float4 dwa = dw4a[g];
            const float4 dwb = dw4b[g];
            const int   idxa[4] = {eia.x, eia.y, eia.z, eia.w};
            const int   idxb[4] = {eib.x, eib.y, eib.z, eib.w};
            const float wa[4]   = {dwa.x, dwa.y, dwa.z, dwa.w};
            const float wb[4]   = {dwb.x, dwb.y, dwb.z, dwb.w};

            #pragma unroll
            for (int j = 0; j < 4; ++j) {
                const float2 pn1 = pxy[idxa[j]];   // LDS.64
                const float2 pn2 = pxy[idxb[j]];
                const float  vn1 = sv[idxa[j]];    // LDS.32
                const float  vn2 = sv[idxb[j]];

                const u64 dx = pk(pn1.x - pc1.x, pn2.x - pc2.x);
                const u64 dy = pk(pn1.y - pc1.y, pn2.y - pc2.y);
                const u64 w  = pk(wa[j], wb[j]);
                const u64 r0 = pk(vn1 - vc1, vn2 - vc2);

                const u64 a0  = mul2(dx, w);
                const u64 a1  = mul2(dy, w);
                const u64 wh  = mul2(w, HALF2);
                const u64 a2  = mul2(mul2(dx, dx), wh);
                const u64 a3  = mul2(mul2(dx, dy), w);
                const u64 a4  = mul2(mul2(dy, dy), wh);
                const u64 r   = mul2(r0, w);
                const u64 a[ND] = {a0, a1, a2, a3, a4};

                #pragma unroll
                for (int i = 0; i < ND; ++i) {
                    #pragma unroll
                    for (int c = i; c < ND; ++c)
                        M[i][c] = fma2(a[i], a[c], M[i][c]);
                    bv[i] = fma2(a[i], r, bv[i]);
                }
            }
        }

        // Ridge on diagonal
        #pragma unroll
        for (int i = 0; i < ND; ++i) M[i][i] = add2(M[i][i], RIDGE2);

        // Packed symmetric Gaussian elimination (upper triangle only; the
        // trailing submatrix stays exactly symmetric under these updates, so
        // this is numerically identical to full unpivoted GE).
        #pragma unroll
        for (int i = 0; i < ND - 1; ++i) {
            const u64 inv = rcp2(M[i][i]);
            #pragma unroll
            for (int r2 = i + 1; r2 < ND; ++r2) {
                const u64 f  = mul2(M[i][r2], inv);
                const u64 nf = f ^ SGN2;
                #pragma unroll
                for (int c = r2; c < ND; ++c)
                    M[r2][c] = fma2(nf, M[i][c], M[r2][c]);
                bv[r2] = fma2(nf, bv[i], bv[r2]);
            }
        }

        // Packed back substitution (keep negated solution to avoid per-term xor)
        u64 nsol[ND];
        u64 du2 = 0ull;
        #pragma unroll
        for (int i = ND - 1; i >= 0; --i) {
            u64 acc = bv[i];
            #pragma unroll
            for (int c = i + 1; c < ND; ++c)
                acc = fma2(M[i][c], nsol[c], acc);   // acc -= M[i][c]*sol[c]
            const u64 soli = mul2(acc, rcp2(M[i][i]));
            nsol[i] = soli ^ SGN2;
            du2 = fma2(soli, wpk[i], du2);
        }

        float du1, duB;
        upk(du1, duB, du2);
        out[(size_t)b * SIZE + s1] = vc1 + dt * du1;
        out[(size_t)b * SIZE + s2] = vc2 + dt * duB;
    }
}

// ---------------------------------------------------------------------------
// Fallback kernel (global-memory gathers, no opt-in smem) — env insurance only
// ---------------------------------------------------------------------------
__global__ void __launch_bounds__(256)
tp_layer_fallback_kernel(const float* __restrict__ x,
                         const float* __restrict__ points,
                         const int*   __restrict__ edge_index,
                         const float* __restrict__ dt_p,
                         const float* __restrict__ dist,
                         const float* __restrict__ weight,
                         float* __restrict__ out,
                         int total)
{
    int gid = blockIdx.x * blockDim.x + threadIdx.x;
    if (gid >= total) return;
    const int b = gid >> 14;
    const int s = gid & (SIZE - 1);

    const float* pts_b = points + (size_t)b * SIZE * 2;
    const float* x_b   = x + (size_t)b * SIZE;
    const float2 pc = *reinterpret_cast<const float2*>(pts_b + 2 * s);
    const float  vc = x_b[s];

    const int4*   ei4 = reinterpret_cast<const int4*>(edge_index + (size_t)b * SIZE * KNN + (size_t)s * KNN);
    const float4* dw4 = reinterpret_cast<const float4*>(dist       + (size_t)b * SIZE * KNN + (size_t)s * KNN);

    float m[ND][ND] = {};
    float bv[ND] = {};
    #pragma unroll
    for (int g = 0; g < 4; ++g) {
        const int4   ei = ei4[g];
        const float4 dw = dw4[g];
        const int   idx[4] = {ei.x, ei.y, ei.z, ei.w};
        const float wts[4] = {dw.x, dw.y, dw.z, dw.w};
        #pragma unroll
        for (int j = 0; j < 4; ++j) {
            const int id = idx[j];
            const float2 pn = *reinterpret_cast<const float2*>(pts_b + 2 * id);
            const float dx = pn.x - pc.x, dy = pn.y - pc.y;
            const float w = wts[j];
            const float a[ND] = {dx*w, dy*w, 0.5f*dx*dx*w, dx*dy*w, 0.5f*dy*dy*w};
            const float r = (x_b[id] - vc) * w;
            #pragma unroll
            for (int i = 0; i < ND; ++i) {
                #pragma unroll
                for (int c = i; c < ND; ++c) m[i][c] += a[i]*a[c];
                bv[i] += a[i]*r;
            }
        }
    }
    #pragma unroll
    for (int i = 0; i < ND; ++i) m[i][i] += 1e-6f;
    #pragma unroll
    for (int i = 0; i < ND - 1; ++i) {
        const float inv = frcp_fast(m[i][i]);
        #pragma unroll
        for (int r2 = i + 1; r2 < ND; ++r2) {
            const float f = m[i][r2] * inv;
            #pragma unroll
            for (int c = r2; c < ND; ++c) m[r2][c] -= f * m[i][c];
            bv[r2] -= f * bv[i];
        }
    }
    float sol[ND];
    float du = 0.f;
    #pragma unroll
    for (int i = ND - 1; i >= 0; --i) {
        float acc = bv[i];
        #pragma unroll
        for (int c = i + 1; c < ND; ++c) acc -= m[i][c] * sol[c];
        sol[i] = acc * frcp_fast(m[i][i]);
        du += sol[i] * weight[i];
    }
    out[gid] = vc + dt_p[0] * du;
}

extern "C" void kernel_launch(void* const* d_in, const int* in_sizes, int n_in,
                              void* d_out, int out_size)
{
    const float* x      = (const float*)d_in[0];
    const float* points = (const float*)d_in[1];
    const int*   eidx   = (const int*)  d_in[2];
    const float* dt     = (const float*)d_in[3];
    const float* dist   = (const float*)d_in[4];
    const float* weight = (const float*)d_in[5];
    float* out = (float*)d_out;

    // Opt-in smem; environment-deterministic, identical on every call.
    cudaError_t attr_ok = cudaFuncSetAttribute(
        tp_layer_smem_kernel,
        cudaFuncAttributeMaxDynamicSharedMemorySize,
        SMEM_BYTES);

    if (attr_ok == cudaSuccess) {
        tp_layer_smem_kernel<<<NBATCH * CHUNKS, NTHREADS, SMEM_BYTES>>>(
            x, points, eidx, dt, dist, weight, out);
    } else {
        const int total = out_size;
        tp_layer_fallback_kernel<<<(total + 255) / 256, 256>>>(
            x, points, eidx, dt, dist, weight, out, total);
    }
}

// round 7
// speedup vs baseline: 1.0022x; 1.0022x over previous
#include <cuda_runtime.h>
#include <cuda_bf16.h>

// Problem constants (match reference)
#define SIZE     16384      // 128*128 points per batch
#define KNN      16
#define ND       5          // num derivatives (order 2, 2D)
#define NBATCH   32
#define TOTAL    (NBATCH * SIZE)   // 524288
#define NCTAS    148        // one CTA per SM, balanced persistent ranges
#define NTHREADS 1024

// Dynamic smem: float2 pxy[SIZE] (128KB) + float sv[SIZE] (64KB)
#define SMEM_BYTES (SIZE * sizeof(float2) + SIZE * sizeof(float))  // 196608

__device__ __forceinline__ float frcp_fast(float x) {
    float r; asm("rcp.approx.f32 %0, %1;" : "=f"(r) : "f"(x)); return r;
}

// ---------------------------------------------------------------------------
// Per-point solve with deferred column scaling:
//   design columns scaled by D = diag(1,1,2,1,2)  (a2 = dx^2 w, a4 = dy^2 w)
//   => ridge scaled by d_i^2, output weights scaled by d_i. Exactly equivalent
//   to the reference's (AtA + 1e-6 I) solve.
// ---------------------------------------------------------------------------
__device__ __forceinline__ float point_du(
    const float2* __restrict__ pxy, const float* __restrict__ sv,
    const int* __restrict__ eidx_g, const float* __restrict__ dist_g,
    const float* __restrict__ wf,   // folded weights {w0,w1,2w2,w3,2w4}
    int s, float2 pc, float vc)
{
    const int4*   ei4 = reinterpret_cast<const int4*>(eidx_g + (size_t)s * KNN);
    const float4* dw4 = reinterpret_cast<const float4*>(dist_g + (size_t)s * KNN);

    // upper-triangle normal equations + rhs
    float m[ND][ND];
    float bv[ND];
    #pragma unroll
    for (int i = 0; i < ND; ++i) {
        bv[i] = 0.f;
        #pragma unroll
        for (int j = i; j < ND; ++j) m[i][j] = 0.f;
    }

    #pragma unroll
    for (int g = 0; g < 4; ++g) {
        const int4   ei = ei4[g];
        const float4 dw = dw4[g];
        const int   idx[4] = {ei.x, ei.y, ei.z, ei.w};
        const float wts[4] = {dw.x, dw.y, dw.z, dw.w};

        #pragma unroll
        for (int j = 0; j < 4; ++j) {
            const int    id = idx[j];
            const float  w  = wts[j];
            const float2 pn = pxy[id];     // LDS.64
            const float  vn = sv[id];      // LDS.32

            const float dx = pn.x - pc.x;
            const float dy = pn.y - pc.y;
            const float a0 = dx * w;
            const float a1 = dy * w;
            const float a2 = dx * a0;      // dx^2 w  (= 2 * original col)
            const float a3 = dy * a0;      // dx dy w
            const float a4 = dy * a1;      // dy^2 w  (= 2 * original col)
            const float r  = (vn - vc) * w;
            const float a[ND] = {a0, a1, a2, a3, a4};

            #pragma unroll
            for (int i = 0; i < ND; ++i) {
                #pragma unroll
                for (int c = i; c < ND; ++c) m[i][c] = fmaf(a[i], a[c], m[i][c]);
                bv[i] = fmaf(a[i], r, bv[i]);
            }
        }
    }

    // ridge scaled by d_i^2
    m[0][0] += 1e-6f; m[1][1] += 1e-6f; m[2][2] += 4e-6f;
    m[3][3] += 1e-6f; m[4][4] += 4e-6f;

    // symmetric unpivoted Gaussian elimination (upper triangle only)
    #pragma unroll
    for (int i = 0; i < ND - 1; ++i) {
        const float inv = frcp_fast(m[i][i]);
        #pragma unroll
        for (int r2 = i + 1; r2 < ND; ++r2) {
            const float f = m[i][r2] * inv;
            #pragma unroll
            for (int c = r2; c < ND; ++c) m[r2][c] = fmaf(-f, m[i][c], m[r2][c]);
            bv[r2] = fmaf(-f, bv[i], bv[r2]);
        }
    }
    // back substitution, accumulate du with folded weights
    float sol[ND];
    float du = 0.f;
    #pragma unroll
    for (int i = ND - 1; i >= 0; --i) {
        float acc = bv[i];
        #pragma unroll
        for (int c = i + 1; c < ND; ++c) acc = fmaf(-m[i][c], sol[c], acc);
        sol[i] = acc * frcp_fast(m[i][i]);
        du = fmaf(sol[i], wf[i], du);
    }
    return du;
}

// ---------------------------------------------------------------------------
// Primary kernel: 148 persistent CTAs with balanced global point ranges.
// Each CTA stages the batch(es) its range touches (<=2) into 192 KB smem.
// ---------------------------------------------------------------------------
__global__ void __launch_bounds__(NTHREADS, 1)
tp_layer_smem_kernel(const float* __restrict__ x,
                     const float* __restrict__ points,
                     const int*   __restrict__ edge_index,
                     const float* __restrict__ dt_p,
                     const float* __restrict__ dist,
                     const float* __restrict__ weight,
                     float* __restrict__ out)
{
    extern __shared__ float smem[];
    float2* pxy = reinterpret_cast<float2*>(smem);   // [SIZE]
    float*  sv  = smem + 2 * SIZE;                    // [SIZE]

    const int tid = threadIdx.x;
    const int bid = blockIdx.x;

    long long g0 = (long long)TOTAL * bid / NCTAS;
    const long long g1 = (long long)TOTAL * (bid + 1) / NCTAS;

    const float dt = dt_p[0];
    // fold D into the output weights: du = sum d_i * y_i * w_i
    float wf[ND];
    wf[0] = weight[0]; wf[1] = weight[1]; wf[2] = 2.f * weight[2];
    wf[3] = weight[3]; wf[4] = 2.f * weight[4];

    while (g0 < g1) {
        const int b   = (int)(g0 >> 14);          // / SIZE
        const int s0  = (int)(g0 & (SIZE - 1));   // % SIZE
        const long long rem = g1 - g0;
        const int seg = (int)((rem < (long long)(SIZE - s0)) ? rem : (SIZE - s0));
        const int s1  = s0 + seg;

        // Stage batch b into smem (coalesced float4 copies; layouts identical).
        const float* pts_b = points + (size_t)b * SIZE * 2;
        const float* x_b   = x + (size_t)b * SIZE;
        {
            float4* dstp = reinterpret_cast<float4*>(pxy);
            const float4* srcp = reinterpret_cast<const float4*>(pts_b);
            #pragma unroll
            for (int i = 0; i < (SIZE * 2 / 4) / NTHREADS; ++i)   // 8 iters
                dstp[tid + i * NTHREADS] = srcp[tid + i * NTHREADS];

            float4* dstx = reinterpret_cast<float4*>(sv);
            const float4* srcx = reinterpret_cast<const float4*>(x_b);
            #pragma unroll
            for (int i = 0; i < (SIZE / 4) / NTHREADS; ++i)       // 4 iters
                dstx[tid + i * NTHREADS] = srcx[tid + i * NTHREADS];
        }
        __syncthreads();

        const int*   eidx_g = edge_index + (size_t)b * SIZE * KNN;
        const float* dist_g = dist       + (size_t)b * SIZE * KNN;

        for (int s = s0 + tid; s < s1; s += NTHREADS) {
            const float2 pc = pxy[s];
            const float  vc = sv[s];
            const float du = point_du(pxy, sv, eidx_g, dist_g, wf, s, pc, vc);
            out[(size_t)b * SIZE + s] = vc + dt * du;
        }
        __syncthreads();   // drain readers before any re-stage overwrites smem
        g0 += seg;
    }
}

// ---------------------------------------------------------------------------
// Fallback kernel (global-memory gathers, no opt-in smem) — env insurance only
// ---------------------------------------------------------------------------
__global__ void __launch_bounds__(256)
tp_layer_fallback_kernel(const float* __restrict__ x,
                         const float* __restrict__ points,
                         const int*   __restrict__ edge_index,
                         const float* __restrict__ dt_p,
                         const float* __restrict__ dist,
                         const float* __restrict__ weight,
                         float* __restrict__ out,
                         int total)
{
    int gid = blockIdx.x * blockDim.x + threadIdx.x;
    if (gid >= total) return;
    const int b = gid >> 14;
    const int s = gid & (SIZE - 1);

    const float* pts_b = points + (size_t)b * SIZE * 2;
    const float* x_b   = x + (size_t)b * SIZE;
    const float2 pc = *reinterpret_cast<const float2*>(pts_b + 2 * s);
    const float  vc = x_b[s];

    const int4*   ei4 = reinterpret_cast<const int4*>(edge_index + (size_t)b * SIZE * KNN + (size_t)s * KNN);
    const float4* dw4 = reinterpret_cast<const float4*>(dist       + (size_t)b * SIZE * KNN + (size_t)s * KNN);

    float m[ND][ND] = {};
    float bv[ND] = {};
    #pragma unroll
    for (int g = 0; g < 4; ++g) {
        const int4   ei = ei4[g];
        const float4 dw = dw4[g];
        const int   idx[4] = {ei.x, ei.y, ei.z, ei.w};
        const float wts[4] = {dw.x, dw.y, dw.z, dw.w};
        #pragma unroll
        for (int j = 0; j < 4; ++j) {
            const int id = idx[j];
            const float2 pn = *reinterpret_cast<const float2*>(pts_b + 2 * id);
            const float dx = pn.x - pc.x, dy = pn.y - pc.y;
            const float w = wts[j];
            const float a0 = dx*w, a1 = dy*w;
            const float a[ND] = {a0, a1, dx*a0, dy*a0, dy*a1};
            const float r = (x_b[id] - vc) * w;
            #pragma unroll
            for (int i = 0; i < ND; ++i) {
                #pragma unroll
                for (int c = i; c < ND; ++c) m[i][c] = fmaf(a[i], a[c], m[i][c]);
                bv[i] = fmaf(a[i], r, bv[i]);
            }
        }
    }
    m[0][0] += 1e-6f; m[1][1] += 1e-6f; m[2][2] += 4e-6f;
    m[3][3] += 1e-6f; m[4][4] += 4e-6f;
    #pragma unroll
    for (int i = 0; i < ND - 1; ++i) {
        const float inv = frcp_fast(m[i][i]);
        #pragma unroll
        for (int r2 = i + 1; r2 < ND; ++r2) {
            const float f = m[i][r2] * inv;
            #pragma unroll
            for (int c = r2; c < ND; ++c) m[r2][c] = fmaf(-f, m[i][c], m[r2][c]);
            bv[r2] = fmaf(-f, bv[i], bv[r2]);
        }
    }
    float sol[ND];
    float du = 0.f;
    const float wf[ND] = {weight[0], weight[1], 2.f*weight[2], weight[3], 2.f*weight[4]};
    #pragma unroll
    for (int i = ND - 1; i >= 0; --i) {
        float acc = bv[i];
        #pragma unroll
        for (int c = i + 1; c < ND; ++c) acc = fmaf(-m[i][c], sol[c], acc);
        sol[i] = acc * frcp_fast(m[i][i]);
        du = fmaf(sol[i], wf[i], du);
    }
    out[gid] = vc + dt_p[0] * du;
}

extern "C" void kernel_launch(void* const* d_in, const int* in_sizes, int n_in,
                              void* d_out, int out_size)
{
    const float* x      = (const float*)d_in[0];
    const float* points = (const float*)d_in[1];
    const int*   eidx   = (const int*)  d_in[2];
    const float* dt     = (const float*)d_in[3];
    const float* dist   = (const float*)d_in[4];
    const float* weight = (const float*)d_in[5];
    float* out = (float*)d_out;

    // Opt-in smem; environment-deterministic, identical on every call.
    cudaError_t attr_ok = cudaFuncSetAttribute(
        tp_layer_smem_kernel,
        cudaFuncAttributeMaxDynamicSharedMemorySize,
        SMEM_BYTES);

    if (attr_ok == cudaSuccess) {
        tp_layer_smem_kernel<<<NCTAS, NTHREADS, SMEM_BYTES>>>(
            x, points, eidx, dt, dist, weight, out);
    } else {
        const int total = out_size;
        tp_layer_fallback_kernel<<<(total + 255) / 256, 256>>>(
            x, points, eidx, dt, dist, weight, out, total);
    }
}

// round 8
// speedup vs baseline: 1.0582x; 1.0559x over previous
#include <cuda_runtime.h>
#include <cuda_bf16.h>

// Problem constants (match reference)
#define SIZE     16384      // 128*128 points per batch
#define KNN      16
#define ND       5          // num derivatives (order 2, 2D)
#define NBATCH   32
#define CHUNKS   4          // CTAs per batch -> grid 128 (single wave)
#define CTA_PTS  (SIZE / CHUNKS)   // 4096 points per CTA
#define NTHREADS 1024
#define PTS_PER_THREAD (CTA_PTS / NTHREADS)  // 4

// Dynamic smem: float2 pxy[SIZE] (128KB) + float sv[SIZE] (64KB)
#define SMEM_BYTES (SIZE * sizeof(float2) + SIZE * sizeof(float))  // 196608

__device__ __forceinline__ float frcp_fast(float x) {
    float r; asm("rcp.approx.f32 %0, %1;" : "=f"(r) : "f"(x)); return r;
}

// ---------------------------------------------------------------------------
// Per-point: accumulate the 12 distinct Gram monomials w^2 dx^p dy^q
// (p+q in [2,4]) + 5 rhs terms, then solve the 5x5 SPD system.
// Columns are scaled by D = diag(1,1,2,1,2) relative to the reference Taylor
// design (q's carry dx^2 w, dy^2 w without the 1/2). Exact equivalence:
// ridge scaled by d_i^2 -> {1,1,4,1,4}*1e-6, output weights scaled by d_i.
// ---------------------------------------------------------------------------
__device__ __forceinline__ float point_du(
    const float2* __restrict__ pxy, const float* __restrict__ sv,
    const int* __restrict__ eidx_g, const float* __restrict__ dist_g,
    const float* __restrict__ wf,   // folded weights {w0,w1,2w2,w3,2w4}
    int s, float2 pc, float vc)
{
    const int4*   ei4 = reinterpret_cast<const int4*>(eidx_g + (size_t)s * KNN);
    const float4* dw4 = reinterpret_cast<const float4*>(dist_g + (size_t)s * KNN);

    float M20=0,M11=0,M02=0;                 // degree-2 monomials
    float M30=0,M21=0,M12=0,M03=0;           // degree-3
    float M40=0,M31=0,M22=0,M13=0,M04=0;     // degree-4
    float b0=0,b1=0,b2=0,b3=0,b4=0;          // rhs

    #pragma unroll
    for (int g = 0; g < 4; ++g) {
        const int4   ei = ei4[g];
        const float4 dw = dw4[g];
        const int   idx[4] = {ei.x, ei.y, ei.z, ei.w};
        const float wts[4] = {dw.x, dw.y, dw.z, dw.w};

        #pragma unroll
        for (int j = 0; j < 4; ++j) {
            const int    id = idx[j];
            const float  w  = wts[j];
            const float2 pn = pxy[id];     // LDS.64
            const float  vn = sv[id];      // LDS.32

            const float dx = pn.x - pc.x;
            const float dy = pn.y - pc.y;
            const float p0 = dx * w;       // w dx
            const float p1 = dy * w;       // w dy
            const float q0 = p0 * dx;      // w dx^2
            const float q1 = p0 * dy;      // w dx dy
            const float q2 = p1 * dy;      // w dy^2
            const float r  = (vn - vc) * w;

            M20 = fmaf(p0, p0, M20); M11 = fmaf(p0, p1, M11); M02 = fmaf(p1, p1, M02);
            M30 = fmaf(q0, p0, M30); M21 = fmaf(q0, p1, M21);
            M12 = fmaf(q1, p1, M12); M03 = fmaf(q2, p1, M03);
            M40 = fmaf(q0, q0, M40); M31 = fmaf(q0, q1, M31); M22 = fmaf(q0, q2, M22);
            M13 = fmaf(q1, q2, M13); M04 = fmaf(q2, q2, M04);
            b0 = fmaf(p0, r, b0); b1 = fmaf(p1, r, b1);
            b2 = fmaf(q0, r, b2); b3 = fmaf(q1, r, b3); b4 = fmaf(q2, r, b4);
        }
    }

    // Expand monomials into the upper-triangular Gram matrix + scaled ridge.
    float m[ND][ND];
    m[0][0]=M20+1e-6f; m[0][1]=M11; m[0][2]=M30; m[0][3]=M21; m[0][4]=M12;
    m[1][1]=M02+1e-6f; m[1][2]=M21; m[1][3]=M12; m[1][4]=M03;
    m[2][2]=M40+4e-6f; m[2][3]=M31; m[2][4]=M22;
    m[3][3]=M22+1e-6f; m[3][4]=M13;
    m[4][4]=M04+4e-6f;
    float bv[ND] = {b0, b1, b2, b3, b4};

    // symmetric unpivoted Gaussian elimination (upper triangle only)
    #pragma unroll
    for (int i = 0; i < ND - 1; ++i) {
        const float inv = frcp_fast(m[i][i]);
        #pragma unroll
        for (int r2 = i + 1; r2 < ND; ++r2) {
            const float f = m[i][r2] * inv;
            #pragma unroll
            for (int c = r2; c < ND; ++c) m[r2][c] = fmaf(-f, m[i][c], m[r2][c]);
            bv[r2] = fmaf(-f, bv[i], bv[r2]);
        }
    }
    // back substitution, accumulate du with folded weights
    float sol[ND];
    float du = 0.f;
    #pragma unroll
    for (int i = ND - 1; i >= 0; --i) {
        float acc = bv[i];
        #pragma unroll
        for (int c = i + 1; c < ND; ++c) acc = fmaf(-m[i][c], sol[c], acc);
        sol[i] = acc * frcp_fast(m[i][i]);
        du = fmaf(sol[i], wf[i], du);
    }
    return du;
}

// ---------------------------------------------------------------------------
// Primary kernel: R5 scaffold — grid 128 (single wave), full batch in 192 KB
// smem, one staging per CTA, static fully-balanced point ranges.
// ---------------------------------------------------------------------------
__global__ void __launch_bounds__(NTHREADS, 1)
tp_layer_smem_kernel(const float* __restrict__ x,
                     const float* __restrict__ points,
                     const int*   __restrict__ edge_index,
                     const float* __restrict__ dt_p,
                     const float* __restrict__ dist,
                     const float* __restrict__ weight,
                     float* __restrict__ out)
{
    extern __shared__ float smem[];
    float2* pxy = reinterpret_cast<float2*>(smem);   // [SIZE]
    float*  sv  = smem + 2 * SIZE;                    // [SIZE]

    const int b     = blockIdx.x / CHUNKS;
    const int chunk = blockIdx.x % CHUNKS;
    const int tid   = threadIdx.x;

    const float* pts_b = points + (size_t)b * SIZE * 2;
    const float* x_b   = x + (size_t)b * SIZE;

    // Stage batch into smem: coalesced float4 copies (layout identical).
    {
        float4* dstp = reinterpret_cast<float4*>(pxy);
        const float4* srcp = reinterpret_cast<const float4*>(pts_b);
        #pragma unroll
        for (int i = 0; i < (SIZE * 2 / 4) / NTHREADS; ++i)   // 8 iters
            dstp[tid + i * NTHREADS] = srcp[tid + i * NTHREADS];

        float4* dstx = reinterpret_cast<float4*>(sv);
        const float4* srcx = reinterpret_cast<const float4*>(x_b);
        #pragma unroll
        for (int i = 0; i < (SIZE / 4) / NTHREADS; ++i)       // 4 iters
            dstx[tid + i * NTHREADS] = srcx[tid + i * NTHREADS];
    }
    __syncthreads();

    const float dt = dt_p[0];
    float wf[ND];
    wf[0] = weight[0]; wf[1] = weight[1]; wf[2] = 2.f * weight[2];
    wf[3] = weight[3]; wf[4] = 2.f * weight[4];

    const int s_base = chunk * CTA_PTS;
    const int*   eidx_g = edge_index + (size_t)b * SIZE * KNN;
    const float* dist_g = dist       + (size_t)b * SIZE * KNN;

    #pragma unroll 1
    for (int p = 0; p < PTS_PER_THREAD; ++p) {
        const int s = s_base + tid + p * NTHREADS;
        const float2 pc = pxy[s];
        const float  vc = sv[s];
        const float du = point_du(pxy, sv, eidx_g, dist_g, wf, s, pc, vc);
        out[(size_t)b * SIZE + s] = vc + dt * du;
    }
}

// ---------------------------------------------------------------------------
// Fallback kernel (global-memory gathers, no opt-in smem) — env insurance only
// ---------------------------------------------------------------------------
__global__ void __launch_bounds__(256)
tp_layer_fallback_kernel(const float* __restrict__ x,
                         const float* __restrict__ points,
                         const int*   __restrict__ edge_index,
                         const float* __restrict__ dt_p,
                         const float* __restrict__ dist,
                         const float* __restrict__ weight,
                         float* __restrict__ out,
                         int total)
{
    int gid = blockIdx.x * blockDim.x + threadIdx.x;
    if (gid >= total) return;
    const int b = gid >> 14;
    const int s = gid & (SIZE - 1);

    const float* pts_b = points + (size_t)b * SIZE * 2;
    const float* x_b   = x + (size_t)b * SIZE;
    const float2 pc = *reinterpret_cast<const float2*>(pts_b + 2 * s);
    const float  vc = x_b[s];

    const int4*   ei4 = reinterpret_cast<const int4*>(edge_index + (size_t)b * SIZE * KNN + (size_t)s * KNN);
    const float4* dw4 = reinterpret_cast<const float4*>(dist       + (size_t)b * SIZE * KNN + (size_t)s * KNN);

    float M20=0,M11=0,M02=0,M30=0,M21=0,M12=0,M03=0,M40=0,M31=0,M22=0,M13=0,M04=0;
    float b0=0,b1=0,b2=0,b3=0,b4=0;
    #pragma unroll
    for (int g = 0; g < 4; ++g) {
        const int4   ei = ei4[g];
        const float4 dw = dw4[g];
        const int   idx[4] = {ei.x, ei.y, ei.z, ei.w};
        const float wts[4] = {dw.x, dw.y, dw.z, dw.w};
        #pragma unroll
        for (int j = 0; j < 4; ++j) {
            const int id = idx[j];
            const float2 pn = *reinterpret_cast<const float2*>(pts_b + 2 * id);
            const float dx = pn.x - pc.x, dy = pn.y - pc.y;
            const float w = wts[j];
            const float p0 = dx*w, p1 = dy*w;
            const float q0 = p0*dx, q1 = p0*dy, q2 = p1*dy;
            const float r = (x_b[id] - vc) * w;
            M20 = fmaf(p0,p0,M20); M11 = fmaf(p0,p1,M11); M02 = fmaf(p1,p1,M02);
            M30 = fmaf(q0,p0,M30); M21 = fmaf(q0,p1,M21);
            M12 = fmaf(q1,p1,M12); M03 = fmaf(q2,p1,M03);
            M40 = fmaf(q0,q0,M40); M31 = fmaf(q0,q1,M31); M22 = fmaf(q0,q2,M22);
            M13 = fmaf(q1,q2,M13); M04 = fmaf(q2,q2,M04);
            b0 = fmaf(p0,r,b0); b1 = fmaf(p1,r,b1);
            b2 = fmaf(q0,r,b2); b3 = fmaf(q1,r,b3); b4 = fmaf(q2,r,b4);
        }
    }
    float m[ND][ND];
    m[0][0]=M20+1e-6f; m[0][1]=M11; m[0][2]=M30; m[0][3]=M21; m[0][4]=M12;
    m[1][1]=M02+1e-6f; m[1][2]=M21; m[1][3]=M12; m[1][4]=M03;
    m[2][2]=M40+4e-6f; m[2][3]=M31; m[2][4]=M22;
    m[3][3]=M22+1e-6f; m[3][4]=M13;
    m[4][4]=M04+4e-6f;
    float bv[ND] = {b0, b1, b2, b3, b4};
    #pragma unroll
    for (int i = 0; i < ND - 1; ++i) {
        const float inv = frcp_fast(m[i][i]);
        #pragma unroll
        for (int r2 = i + 1; r2 < ND; ++r2) {
            const float f = m[i][r2] * inv;
            #pragma unroll
            for (int c = r2; c < ND; ++c) m[r2][c] = fmaf(-f, m[i][c], m[r2][c]);
            bv[r2] = fmaf(-f, bv[i], bv[r2]);
        }
    }
    float sol[ND];
    float du = 0.f;
    const float wf[ND] = {weight[0], weight[1], 2.f*weight[2], weight[3], 2.f*weight[4]};
    #pragma unroll
    for (int i = ND - 1; i >= 0; --i) {
        float acc = bv[i];
        #pragma unroll
        for (int c = i + 1; c < ND; ++c) acc = fmaf(-m[i][c], sol[c], acc);
        sol[i] = acc * frcp_fast(m[i][i]);
        du = fmaf(sol[i], wf[i], du);
    }
    out[gid] = vc + dt_p[0] * du;
}

extern "C" void kernel_launch(void* const* d_in, const int* in_sizes, int n_in,
                              void* d_out, int out_size)
{
    const float* x      = (const float*)d_in[0];
    const float* points = (const float*)d_in[1];
    const int*   eidx   = (const int*)  d_in[2];
    const float* dt     = (const float*)d_in[3];
    const float* dist   = (const float*)d_in[4];
    const float* weight = (const float*)d_in[5];
    float* out = (float*)d_out;

    // Opt-in smem; environment-deterministic, identical on every call.
    cudaError_t attr_ok = cudaFuncSetAttribute(
        tp_layer_smem_kernel,
        cudaFuncAttributeMaxDynamicSharedMemorySize,
        SMEM_BYTES);

    if (attr_ok == cudaSuccess) {
        tp_layer_smem_kernel<<<NBATCH * CHUNKS, NTHREADS, SMEM_BYTES>>>(
            x, points, eidx, dt, dist, weight, out);
    } else {
        const int total = out_size;
        tp_layer_fallback_kernel<<<(total + 255) / 256, 256>>>(
            x, points, eidx, dt, dist, weight, out, total);
    }
}